// round 3
// baseline (speedup 1.0000x reference)
#include <cuda_runtime.h>
#include <cuda_fp16.h>
#include <math.h>

#define NN 50000
#define EE 800000
#define EPD 850000   // E + N self loops
#define HH 8
#define CC 16
#define HC 128       // H*C

// ---------------- scratch (device globals; no allocation allowed) ----------------
__device__ __align__(16) float  g_h1[(size_t)NN * HC];
__device__ __align__(16) float  g_hA[(size_t)NN * HC];
__device__ __align__(16) float  g_hB[(size_t)NN * HC];
__device__ __align__(16) float  g_z [(size_t)NN * HC];
__device__ __align__(16) __half g_zsh[(size_t)NN * HC];   // fp16 z_scale for edge gathers
__device__ __align__(16) float  g_ae[(size_t)EPD * HH];
__device__ __align__(16) float  g_deg[(size_t)NN * HH];

__device__ __forceinline__ float eluf(float x) { return x > 0.f ? x : expm1f(x); }
__device__ __forceinline__ float softplusf(float x) {
    return x > 0.f ? x + log1pf(expf(-x)) : log1pf(expf(x));
}
__device__ __forceinline__ void store_half4(__half* dst, float4 v) {
    __half2 a = __floats2half2_rn(v.x, v.y);
    __half2 b = __floats2half2_rn(v.z, v.w);
    uint2 u;
    u.x = *(unsigned*)&a; u.y = *(unsigned*)&b;
    *(uint2*)dst = u;
}

// ---------------- initial zero: hB (hop-1 scatter target) + deg -------------------
__global__ void zero0_kernel()
{
    int i = blockIdx.x * blockDim.x + threadIdx.x;
    int stride = gridDim.x * blockDim.x;
    float4 z4 = make_float4(0.f, 0.f, 0.f, 0.f);
    for (int j = i; j < NN * HC / 4; j += stride) *(float4*)&g_hB[j * 4] = z4;
    for (int j = i; j < NN * HH / 4; j += stride) *(float4*)&g_deg[j * 4] = z4;
}

// ---------------- GEMM1: g_h1 = elu(x @ W0 + b0)  (K=256) -------------------------
__global__ void gemm1_kernel(const float* __restrict__ A, const float* __restrict__ W,
                             const float* __restrict__ bias)
{
    __shared__ float As[16][65];
    __shared__ float Bs[16][128];
    const int tid = threadIdx.x;
    const int block_row = blockIdx.x * 64;
    const int row_t = tid >> 5;
    const int col_t = tid & 31;

    float acc[8][4];
    #pragma unroll
    for (int j = 0; j < 8; j++) { acc[j][0]=acc[j][1]=acc[j][2]=acc[j][3]=0.f; }

    for (int k0 = 0; k0 < 256; k0 += 16) {
        {
            int r  = tid >> 2;
            int kk = (tid & 3) << 2;
            int grow = block_row + r;
            float4 v = make_float4(0.f,0.f,0.f,0.f);
            if (grow < NN) v = *(const float4*)&A[(size_t)grow * 256 + k0 + kk];
            As[kk+0][r] = v.x; As[kk+1][r] = v.y; As[kk+2][r] = v.z; As[kk+3][r] = v.w;
        }
        #pragma unroll
        for (int i = 0; i < 2; i++) {
            int idx = tid + (i << 8);
            int bk  = idx >> 5;
            int cc  = (idx & 31) << 2;
            *(float4*)&Bs[bk][cc] = *(const float4*)&W[(size_t)(k0 + bk) * HC + cc];
        }
        __syncthreads();
        #pragma unroll
        for (int k = 0; k < 16; k++) {
            float4 b4 = *(float4*)&Bs[k][col_t << 2];
            #pragma unroll
            for (int j = 0; j < 8; j++) {
                float a = As[k][(row_t << 3) + j];
                acc[j][0] = fmaf(a, b4.x, acc[j][0]);
                acc[j][1] = fmaf(a, b4.y, acc[j][1]);
                acc[j][2] = fmaf(a, b4.z, acc[j][2]);
                acc[j][3] = fmaf(a, b4.w, acc[j][3]);
            }
        }
        __syncthreads();
    }
    float4 bb = *(const float4*)&bias[col_t << 2];
    #pragma unroll
    for (int j = 0; j < 8; j++) {
        int grow = block_row + (row_t << 3) + j;
        if (grow < NN) {
            float4 o;
            o.x = eluf(acc[j][0] + bb.x); o.y = eluf(acc[j][1] + bb.y);
            o.z = eluf(acc[j][2] + bb.z); o.w = eluf(acc[j][3] + bb.w);
            *(float4*)&g_h1[(size_t)grow * HC + (col_t << 2)] = o;
        }
    }
}

// ---------------- GEMM2 + hop-0 epilogue ------------------------------------------
// h = g_h1 @ W1 + b1 -> g_hA ; g = <hop_att0, elu(h)> + bias0 ; z = h*g -> g_z
// zs = z*decay0 -> g_zsh (fp16)
__global__ void gemm2_hop0_kernel(const float* __restrict__ W,
                                  const float* __restrict__ bias,
                                  const float* __restrict__ hop_att0,
                                  const float* __restrict__ hop_bias0,
                                  float decay0)
{
    __shared__ float As[16][65];
    __shared__ float Bs[16][128];
    const int tid = threadIdx.x;
    const int block_row = blockIdx.x * 64;
    const int row_t = tid >> 5;
    const int col_t = tid & 31;

    float acc[8][4];
    #pragma unroll
    for (int j = 0; j < 8; j++) { acc[j][0]=acc[j][1]=acc[j][2]=acc[j][3]=0.f; }

    for (int k0 = 0; k0 < 128; k0 += 16) {
        {
            int r  = tid >> 2;
            int kk = (tid & 3) << 2;
            int grow = block_row + r;
            float4 v = make_float4(0.f,0.f,0.f,0.f);
            if (grow < NN) v = *(const float4*)&g_h1[(size_t)grow * HC + k0 + kk];
            As[kk+0][r] = v.x; As[kk+1][r] = v.y; As[kk+2][r] = v.z; As[kk+3][r] = v.w;
        }
        #pragma unroll
        for (int i = 0; i < 2; i++) {
            int idx = tid + (i << 8);
            int bk  = idx >> 5;
            int cc  = (idx & 31) << 2;
            *(float4*)&Bs[bk][cc] = *(const float4*)&W[(size_t)(k0 + bk) * HC + cc];
        }
        __syncthreads();
        #pragma unroll
        for (int k = 0; k < 16; k++) {
            float4 b4 = *(float4*)&Bs[k][col_t << 2];
            #pragma unroll
            for (int j = 0; j < 8; j++) {
                float a = As[k][(row_t << 3) + j];
                acc[j][0] = fmaf(a, b4.x, acc[j][0]);
                acc[j][1] = fmaf(a, b4.y, acc[j][1]);
                acc[j][2] = fmaf(a, b4.z, acc[j][2]);
                acc[j][3] = fmaf(a, b4.w, acc[j][3]);
            }
        }
        __syncthreads();
    }
    // hop-0 epilogue: warp row_t owns rows [block_row + row_t*8, +8), lane=col_t
    float4 bb = *(const float4*)&bias[col_t << 2];
    const int head = col_t >> 2, sub = col_t & 3;
    const float* av = hop_att0 + head * CC + (sub << 2);
    const float av0 = av[0], av1 = av[1], av2 = av[2], av3 = av[3];
    const float hb = hop_bias0[head];
    #pragma unroll
    for (int j = 0; j < 8; j++) {
        int grow = block_row + (row_t << 3) + j;     // uniform per warp
        if (grow < NN) {
            float4 h4;
            h4.x = acc[j][0] + bb.x; h4.y = acc[j][1] + bb.y;
            h4.z = acc[j][2] + bb.z; h4.w = acc[j][3] + bb.w;
            float p = eluf(h4.x)*av0 + eluf(h4.y)*av1 + eluf(h4.z)*av2 + eluf(h4.w)*av3;
            p += __shfl_xor_sync(0xffffffffu, p, 1);
            p += __shfl_xor_sync(0xffffffffu, p, 2);
            float g = p + hb;
            size_t off = (size_t)grow * HC + (col_t << 2);
            *(float4*)&g_hA[off] = h4;
            float4 z4 = make_float4(h4.x*g, h4.y*g, h4.z*g, h4.w*g);
            *(float4*)&g_z[off] = z4;
            store_half4(&g_zsh[off], make_float4(z4.x*decay0, z4.y*decay0,
                                                 z4.z*decay0, z4.w*decay0));
        }
    }
}

// ---------------- edge attention: a = softplus(<atts, elu(zs_i+zs_j)>)+1e-6 -------
__global__ void edge_att_kernel(const int* __restrict__ ei,
                                const float* __restrict__ atts_k)
{
    int e = (blockIdx.x * blockDim.x + threadIdx.x) >> 5;
    int lane = threadIdx.x & 31;
    if (e >= EPD) return;
    int r, c;
    if (e < EE) { r = ei[e]; c = ei[EE + e]; }
    else        { r = c = e - EE; }
    int head = lane >> 2, sub = lane & 3;
    uint2 ui = *(const uint2*)&g_zsh[(size_t)c * HC + (lane << 2)];
    uint2 uj = *(const uint2*)&g_zsh[(size_t)r * HC + (lane << 2)];
    float2 i0 = __half22float2(*(__half2*)&ui.x);
    float2 i1 = __half22float2(*(__half2*)&ui.y);
    float2 j0 = __half22float2(*(__half2*)&uj.x);
    float2 j1 = __half22float2(*(__half2*)&uj.y);
    const float* av = atts_k + head * CC + (sub << 2);
    float p = eluf(i0.x + j0.x)*av[0] + eluf(i0.y + j0.y)*av[1]
            + eluf(i1.x + j1.x)*av[2] + eluf(i1.y + j1.y)*av[3];
    p += __shfl_xor_sync(0xffffffffu, p, 1);
    p += __shfl_xor_sync(0xffffffffu, p, 2);
    if (sub == 0) {
        float a = softplusf(p) + 1e-6f;
        g_ae[(size_t)e * HH + head] = a;
        atomicAdd(&g_deg[(size_t)c * HH + head], a);
    }
}

// ---------------- propagate: h_new[col] += (deg_r^-.5 * a * deg_c^-.5)*h_prev[row] -
__global__ void prop_kernel(const int* __restrict__ ei, int flip)
{
    const float* hprev = flip ? g_hA : g_hB;   // flip=1: prev A -> new B
    float* hnew        = flip ? g_hB : g_hA;
    int e = (blockIdx.x * blockDim.x + threadIdx.x) >> 5;
    int lane = threadIdx.x & 31;
    if (e >= EPD) return;
    int r, c;
    if (e < EE) { r = ei[e]; c = ei[EE + e]; }
    else        { r = c = e - EE; }
    int head = lane >> 2;
    float dr = g_deg[(size_t)r * HH + head];
    float dc = g_deg[(size_t)c * HH + head];
    float a = g_ae[(size_t)e * HH + head]
            * (dr > 0.f ? rsqrtf(dr) : 0.f)
            * (dc > 0.f ? rsqrtf(dc) : 0.f);
    float4 h4 = *(const float4*)&hprev[(size_t)r * HC + (lane << 2)];
    float* dst = &hnew[(size_t)c * HC + (lane << 2)];
    asm volatile("red.global.add.v4.f32 [%0], {%1,%2,%3,%4};"
                 :: "l"(dst), "f"(a * h4.x), "f"(a * h4.y), "f"(a * h4.z), "f"(a * h4.w)
                 : "memory");
}

// ---------------- hop update: g from elu(concat(h_new, z*decay_prev)); z += h*g ---
// also zeroes the dead h buffer + deg for the next hop (do_zero)
__global__ void hopupd_kernel(const float* __restrict__ hop_atts_k,
                              const float* __restrict__ hop_bias_k,
                              float decay_prev, float decayk, int flip, int do_zero)
{
    const float* hnew = flip ? g_hB : g_hA;
    float* dead       = flip ? g_hA : g_hB;
    int gtid = blockIdx.x * blockDim.x + threadIdx.x;

    if (do_zero) {
        float4 z4 = make_float4(0.f, 0.f, 0.f, 0.f);
        if (gtid * 4 < NN * HC) *(float4*)&dead[gtid * 4] = z4;      // exact cover
        if (gtid < NN * HH / 4) *(float4*)&g_deg[gtid * 4] = z4;
    }

    int w = gtid >> 5;
    int lane = threadIdx.x & 31;
    if (w >= NN) return;
    int head = lane >> 2, sub = lane & 3;
    size_t off = (size_t)w * HC + (lane << 2);
    float4 h4 = *(const float4*)&hnew[off];
    float4 z4 = *(const float4*)&g_z[off];
    float4 zs4 = make_float4(z4.x*decay_prev, z4.y*decay_prev,
                             z4.z*decay_prev, z4.w*decay_prev);
    const float* aw  = hop_atts_k + head * (2 * CC) + (sub << 2);
    const float* aw2 = aw + CC;
    float p = eluf(h4.x)*aw[0]   + eluf(h4.y)*aw[1]   + eluf(h4.z)*aw[2]   + eluf(h4.w)*aw[3]
            + eluf(zs4.x)*aw2[0] + eluf(zs4.y)*aw2[1] + eluf(zs4.z)*aw2[2] + eluf(zs4.w)*aw2[3];
    p += __shfl_xor_sync(0xffffffffu, p, 1);
    p += __shfl_xor_sync(0xffffffffu, p, 2);
    float g = p + hop_bias_k[head];
    z4.x = fmaf(h4.x, g, z4.x);
    z4.y = fmaf(h4.y, g, z4.y);
    z4.z = fmaf(h4.z, g, z4.z);
    z4.w = fmaf(h4.w, g, z4.w);
    *(float4*)&g_z[off] = z4;
    store_half4(&g_zsh[off], make_float4(z4.x*decayk, z4.y*decayk,
                                         z4.z*decayk, z4.w*decayk));
}

// ---------------- output: out = elu(z) @ Wout + bout  (N x 40) --------------------
__global__ void out_kernel(const float* __restrict__ Wout,
                           const float* __restrict__ bout,
                           float* __restrict__ out)
{
    __shared__ float Ws[HC * 40];
    __shared__ float bs[40];
    __shared__ float zsm[8][HC];
    int tid = threadIdx.x;
    for (int i = tid; i < HC * 40; i += 320) Ws[i] = Wout[i];
    if (tid < 40) bs[tid] = bout[tid];
    int nbase = blockIdx.x * 8;
    for (int i = tid; i < 8 * HC; i += 320) {
        int ln = i >> 7, c = i & 127;
        int gn = nbase + ln;
        float v = (gn < NN) ? g_z[(size_t)gn * HC + c] : 0.f;
        zsm[ln][c] = eluf(v);
    }
    __syncthreads();
    int ln = tid / 40, o = tid % 40;
    if (ln < 8) {
        int gn = nbase + ln;
        if (gn < NN) {
            float acc = bs[o];
            #pragma unroll 8
            for (int c = 0; c < HC; c++) acc = fmaf(zsm[ln][c], Ws[c * 40 + o], acc);
            out[(size_t)gn * 40 + o] = acc;
        }
    }
}

// ---------------- host orchestration ----------------------------------------------
extern "C" void kernel_launch(void* const* d_in, const int* in_sizes, int n_in,
                              void* d_out, int out_size)
{
    const float* x          = (const float*)d_in[0];
    const int*   ei         = (const int*)d_in[1];
    const float* W0         = (const float*)d_in[2];
    const float* b0         = (const float*)d_in[3];
    const float* W1         = (const float*)d_in[4];
    const float* b1         = (const float*)d_in[5];
    const float* Wout       = (const float*)d_in[6];
    const float* bout       = (const float*)d_in[7];
    const float* hop_att0   = (const float*)d_in[8];
    const float* hop_atts   = (const float*)d_in[9];
    const float* atts       = (const float*)d_in[10];
    const float* hop_biases = (const float*)d_in[11];
    float* out = (float*)d_out;

    float decay[5];
    for (int k = 0; k <= 4; k++) decay[k] = (float)log(1.0 / (k + 1) + 1.0 + 1e-6);

    const int GEMM_GRID = (NN + 63) / 64;
    const int NODE_GRID = (NN + 7) / 8;          // warp per node, 8 warps/block
    const int EDGE_GRID = (EPD + 7) / 8;         // warp per edge, 8 warps/block

    zero0_kernel<<<2048, 256>>>();                                   // idx 0
    gemm1_kernel<<<GEMM_GRID, 256>>>(x, W0, b0);                     // idx 1
    gemm2_hop0_kernel<<<GEMM_GRID, 256>>>(W1, b1, hop_att0,
                                          hop_biases, decay[0]);     // idx 2

    for (int k = 1; k <= 4; k++) {
        int flip = (k & 1);
        edge_att_kernel<<<EDGE_GRID, 256>>>(ei, atts + (size_t)(k - 1) * HH * CC);
        prop_kernel<<<EDGE_GRID, 256>>>(ei, flip);
        hopupd_kernel<<<NODE_GRID, 256>>>(hop_atts + (size_t)(k - 1) * HH * 2 * CC,
                                          hop_biases + (size_t)k * HH,
                                          decay[k - 1], decay[k], flip,
                                          (k < 4) ? 1 : 0);
    }

    out_kernel<<<(NN + 7) / 8, 320>>>(Wout, bout, out);
}

// round 4
// speedup vs baseline: 1.5995x; 1.5995x over previous
#include <cuda_runtime.h>
#include <math.h>

#define NN 50000
#define EE 800000
#define EPD 850000   // E + N self loops
#define HH 8
#define CC 16
#define HC 128       // H*C

// ---------------- scratch (device globals; no allocation allowed) ----------------
__device__ __align__(16) float g_h1[(size_t)NN * HC];
__device__ __align__(16) float g_hA[(size_t)NN * HC];
__device__ __align__(16) float g_hB[(size_t)NN * HC];
__device__ __align__(16) float g_z [(size_t)NN * HC];
__device__ __align__(16) float g_zs[(size_t)NN * HC];
__device__ __align__(16) float g_ae[(size_t)EPD * HH];
__device__ __align__(16) float g_deg[(size_t)NN * HH];

// fast ELU: 3 instructions on the negative path (FMUL + MUFU.EX2 + FADD)
__device__ __forceinline__ float eluf(float x) {
    return x > 0.f ? x : __expf(x) - 1.f;
}
// fast softplus: max(x,0) + log1p(exp(-|x|)) with MUFU exp/log
__device__ __forceinline__ float softplusf(float x) {
    return fmaxf(x, 0.f) + __logf(1.f + __expf(-fabsf(x)));
}

// ---------------- initial zero: hB (hop-1 scatter target) + deg -------------------
__global__ void zero0_kernel()
{
    int i = blockIdx.x * blockDim.x + threadIdx.x;
    int stride = gridDim.x * blockDim.x;
    float4 z4 = make_float4(0.f, 0.f, 0.f, 0.f);
    for (int j = i; j < NN * HC / 4; j += stride) *(float4*)&g_hB[j * 4] = z4;
    for (int j = i; j < NN * HH / 4; j += stride) *(float4*)&g_deg[j * 4] = z4;
}

// ---------------- GEMM1: g_h1 = elu(x @ W0 + b0)  (K=256) -------------------------
__global__ void gemm1_kernel(const float* __restrict__ A, const float* __restrict__ W,
                             const float* __restrict__ bias)
{
    __shared__ float As[16][65];
    __shared__ float Bs[16][128];
    const int tid = threadIdx.x;
    const int block_row = blockIdx.x * 64;
    const int row_t = tid >> 5;
    const int col_t = tid & 31;

    float acc[8][4];
    #pragma unroll
    for (int j = 0; j < 8; j++) { acc[j][0]=acc[j][1]=acc[j][2]=acc[j][3]=0.f; }

    for (int k0 = 0; k0 < 256; k0 += 16) {
        {
            int r  = tid >> 2;
            int kk = (tid & 3) << 2;
            int grow = block_row + r;
            float4 v = make_float4(0.f,0.f,0.f,0.f);
            if (grow < NN) v = *(const float4*)&A[(size_t)grow * 256 + k0 + kk];
            As[kk+0][r] = v.x; As[kk+1][r] = v.y; As[kk+2][r] = v.z; As[kk+3][r] = v.w;
        }
        #pragma unroll
        for (int i = 0; i < 2; i++) {
            int idx = tid + (i << 8);
            int bk  = idx >> 5;
            int cc  = (idx & 31) << 2;
            *(float4*)&Bs[bk][cc] = *(const float4*)&W[(size_t)(k0 + bk) * HC + cc];
        }
        __syncthreads();
        #pragma unroll
        for (int k = 0; k < 16; k++) {
            float4 b4 = *(float4*)&Bs[k][col_t << 2];
            #pragma unroll
            for (int j = 0; j < 8; j++) {
                float a = As[k][(row_t << 3) + j];
                acc[j][0] = fmaf(a, b4.x, acc[j][0]);
                acc[j][1] = fmaf(a, b4.y, acc[j][1]);
                acc[j][2] = fmaf(a, b4.z, acc[j][2]);
                acc[j][3] = fmaf(a, b4.w, acc[j][3]);
            }
        }
        __syncthreads();
    }
    float4 bb = *(const float4*)&bias[col_t << 2];
    #pragma unroll
    for (int j = 0; j < 8; j++) {
        int grow = block_row + (row_t << 3) + j;
        if (grow < NN) {
            float4 o;
            o.x = eluf(acc[j][0] + bb.x); o.y = eluf(acc[j][1] + bb.y);
            o.z = eluf(acc[j][2] + bb.z); o.w = eluf(acc[j][3] + bb.w);
            *(float4*)&g_h1[(size_t)grow * HC + (col_t << 2)] = o;
        }
    }
}

// ---------------- GEMM2 + hop-0 epilogue ------------------------------------------
// h = g_h1 @ W1 + b1 -> g_hA ; g = <hop_att0, elu(h)> + bias0 ; z = h*g -> g_z
// zs = z*decay0 -> g_zs
__global__ void gemm2_hop0_kernel(const float* __restrict__ W,
                                  const float* __restrict__ bias,
                                  const float* __restrict__ hop_att0,
                                  const float* __restrict__ hop_bias0,
                                  float decay0)
{
    __shared__ float As[16][65];
    __shared__ float Bs[16][128];
    const int tid = threadIdx.x;
    const int block_row = blockIdx.x * 64;
    const int row_t = tid >> 5;
    const int col_t = tid & 31;

    float acc[8][4];
    #pragma unroll
    for (int j = 0; j < 8; j++) { acc[j][0]=acc[j][1]=acc[j][2]=acc[j][3]=0.f; }

    for (int k0 = 0; k0 < 128; k0 += 16) {
        {
            int r  = tid >> 2;
            int kk = (tid & 3) << 2;
            int grow = block_row + r;
            float4 v = make_float4(0.f,0.f,0.f,0.f);
            if (grow < NN) v = *(const float4*)&g_h1[(size_t)grow * HC + k0 + kk];
            As[kk+0][r] = v.x; As[kk+1][r] = v.y; As[kk+2][r] = v.z; As[kk+3][r] = v.w;
        }
        #pragma unroll
        for (int i = 0; i < 2; i++) {
            int idx = tid + (i << 8);
            int bk  = idx >> 5;
            int cc  = (idx & 31) << 2;
            *(float4*)&Bs[bk][cc] = *(const float4*)&W[(size_t)(k0 + bk) * HC + cc];
        }
        __syncthreads();
        #pragma unroll
        for (int k = 0; k < 16; k++) {
            float4 b4 = *(float4*)&Bs[k][col_t << 2];
            #pragma unroll
            for (int j = 0; j < 8; j++) {
                float a = As[k][(row_t << 3) + j];
                acc[j][0] = fmaf(a, b4.x, acc[j][0]);
                acc[j][1] = fmaf(a, b4.y, acc[j][1]);
                acc[j][2] = fmaf(a, b4.z, acc[j][2]);
                acc[j][3] = fmaf(a, b4.w, acc[j][3]);
            }
        }
        __syncthreads();
    }
    // hop-0 epilogue: warp row_t owns rows [block_row + row_t*8, +8), lane=col_t
    float4 bb = *(const float4*)&bias[col_t << 2];
    const int head = col_t >> 2, sub = col_t & 3;
    const float* av = hop_att0 + head * CC + (sub << 2);
    const float av0 = av[0], av1 = av[1], av2 = av[2], av3 = av[3];
    const float hb = hop_bias0[head];
    #pragma unroll
    for (int j = 0; j < 8; j++) {
        int grow = block_row + (row_t << 3) + j;     // uniform per warp
        if (grow < NN) {
            float4 h4;
            h4.x = acc[j][0] + bb.x; h4.y = acc[j][1] + bb.y;
            h4.z = acc[j][2] + bb.z; h4.w = acc[j][3] + bb.w;
            float p = eluf(h4.x)*av0 + eluf(h4.y)*av1 + eluf(h4.z)*av2 + eluf(h4.w)*av3;
            p += __shfl_xor_sync(0xffffffffu, p, 1);
            p += __shfl_xor_sync(0xffffffffu, p, 2);
            float g = p + hb;
            size_t off = (size_t)grow * HC + (col_t << 2);
            *(float4*)&g_hA[off] = h4;
            float4 z4 = make_float4(h4.x*g, h4.y*g, h4.z*g, h4.w*g);
            *(float4*)&g_z[off] = z4;
            *(float4*)&g_zs[off] = make_float4(z4.x*decay0, z4.y*decay0,
                                               z4.z*decay0, z4.w*decay0);
        }
    }
}

// ---------------- edge attention: a = softplus(<atts, elu(zs_i+zs_j)>)+1e-6 -------
// warp-persistent: each warp loops over edges, att weights hoisted
__global__ void edge_att_kernel(const int* __restrict__ ei,
                                const float* __restrict__ atts_k)
{
    const int lane = threadIdx.x & 31;
    const int warp0 = (blockIdx.x * blockDim.x + threadIdx.x) >> 5;
    const int nwarps = (gridDim.x * blockDim.x) >> 5;
    const int head = lane >> 2, sub = lane & 3;
    const float* av = atts_k + head * CC + (sub << 2);
    const float av0 = av[0], av1 = av[1], av2 = av[2], av3 = av[3];

    for (int e = warp0; e < EPD; e += nwarps) {
        int r, c;
        if (e < EE) { r = __ldg(&ei[e]); c = __ldg(&ei[EE + e]); }
        else        { r = c = e - EE; }
        float4 zi = *(const float4*)&g_zs[(size_t)c * HC + (lane << 2)];
        float4 zj = *(const float4*)&g_zs[(size_t)r * HC + (lane << 2)];
        float p = eluf(zi.x + zj.x)*av0 + eluf(zi.y + zj.y)*av1
                + eluf(zi.z + zj.z)*av2 + eluf(zi.w + zj.w)*av3;
        p += __shfl_xor_sync(0xffffffffu, p, 1);
        p += __shfl_xor_sync(0xffffffffu, p, 2);
        if (sub == 0) {
            float a = softplusf(p) + 1e-6f;
            g_ae[(size_t)e * HH + head] = a;
            atomicAdd(&g_deg[(size_t)c * HH + head], a);
        }
    }
}

// ---------------- propagate: h_new[col] += (deg_r^-.5 * a * deg_c^-.5)*h_prev[row] -
__global__ void prop_kernel(const int* __restrict__ ei, int flip)
{
    const float* hprev = flip ? g_hA : g_hB;   // flip=1: prev A -> new B
    float* hnew        = flip ? g_hB : g_hA;
    const int lane = threadIdx.x & 31;
    const int warp0 = (blockIdx.x * blockDim.x + threadIdx.x) >> 5;
    const int nwarps = (gridDim.x * blockDim.x) >> 5;
    const int head = lane >> 2;

    for (int e = warp0; e < EPD; e += nwarps) {
        int r, c;
        if (e < EE) { r = __ldg(&ei[e]); c = __ldg(&ei[EE + e]); }
        else        { r = c = e - EE; }
        float dr = g_deg[(size_t)r * HH + head];
        float dc = g_deg[(size_t)c * HH + head];
        float a = g_ae[(size_t)e * HH + head]
                * (dr > 0.f ? rsqrtf(dr) : 0.f)
                * (dc > 0.f ? rsqrtf(dc) : 0.f);
        float4 h4 = *(const float4*)&hprev[(size_t)r * HC + (lane << 2)];
        float* dst = &hnew[(size_t)c * HC + (lane << 2)];
        asm volatile("red.global.add.v4.f32 [%0], {%1,%2,%3,%4};"
                     :: "l"(dst), "f"(a * h4.x), "f"(a * h4.y), "f"(a * h4.z), "f"(a * h4.w)
                     : "memory");
    }
}

// ---------------- hop update: g from elu(concat(h_new, z*decay_prev)); z += h*g ---
// also zeroes the dead h buffer + deg for the next hop (do_zero)
__global__ void hopupd_kernel(const float* __restrict__ hop_atts_k,
                              const float* __restrict__ hop_bias_k,
                              float decay_prev, float decayk, int flip, int do_zero)
{
    const float* hnew = flip ? g_hB : g_hA;
    float* dead       = flip ? g_hA : g_hB;
    int gtid = blockIdx.x * blockDim.x + threadIdx.x;

    if (do_zero) {
        float4 z4 = make_float4(0.f, 0.f, 0.f, 0.f);
        if (gtid * 4 < NN * HC) *(float4*)&dead[gtid * 4] = z4;      // exact cover
        if (gtid < NN * HH / 4) *(float4*)&g_deg[gtid * 4] = z4;
    }

    int w = gtid >> 5;
    int lane = threadIdx.x & 31;
    if (w >= NN) return;
    int head = lane >> 2, sub = lane & 3;
    size_t off = (size_t)w * HC + (lane << 2);
    float4 h4 = *(const float4*)&hnew[off];
    float4 z4 = *(const float4*)&g_z[off];
    float4 zs4 = make_float4(z4.x*decay_prev, z4.y*decay_prev,
                             z4.z*decay_prev, z4.w*decay_prev);
    const float* aw  = hop_atts_k + head * (2 * CC) + (sub << 2);
    const float* aw2 = aw + CC;
    float p = eluf(h4.x)*aw[0]   + eluf(h4.y)*aw[1]   + eluf(h4.z)*aw[2]   + eluf(h4.w)*aw[3]
            + eluf(zs4.x)*aw2[0] + eluf(zs4.y)*aw2[1] + eluf(zs4.z)*aw2[2] + eluf(zs4.w)*aw2[3];
    p += __shfl_xor_sync(0xffffffffu, p, 1);
    p += __shfl_xor_sync(0xffffffffu, p, 2);
    float g = p + hop_bias_k[head];
    z4.x = fmaf(h4.x, g, z4.x);
    z4.y = fmaf(h4.y, g, z4.y);
    z4.z = fmaf(h4.z, g, z4.z);
    z4.w = fmaf(h4.w, g, z4.w);
    *(float4*)&g_z[off] = z4;
    *(float4*)&g_zs[off] = make_float4(z4.x*decayk, z4.y*decayk,
                                       z4.z*decayk, z4.w*decayk);
}

// ---------------- output: out = elu(z) @ Wout + bout  (N x 40) --------------------
__global__ void out_kernel(const float* __restrict__ Wout,
                           const float* __restrict__ bout,
                           float* __restrict__ out)
{
    __shared__ float Ws[HC * 40];
    __shared__ float bs[40];
    __shared__ float zsm[8][HC];
    int tid = threadIdx.x;
    for (int i = tid; i < HC * 40; i += 320) Ws[i] = Wout[i];
    if (tid < 40) bs[tid] = bout[tid];
    int nbase = blockIdx.x * 8;
    for (int i = tid; i < 8 * HC; i += 320) {
        int ln = i >> 7, c = i & 127;
        int gn = nbase + ln;
        float v = (gn < NN) ? g_z[(size_t)gn * HC + c] : 0.f;
        zsm[ln][c] = eluf(v);
    }
    __syncthreads();
    int ln = tid / 40, o = tid % 40;
    if (ln < 8) {
        int gn = nbase + ln;
        if (gn < NN) {
            float acc = bs[o];
            #pragma unroll 8
            for (int c = 0; c < HC; c++) acc = fmaf(zsm[ln][c], Ws[c * 40 + o], acc);
            out[(size_t)gn * 40 + o] = acc;
        }
    }
}

// ---------------- host orchestration ----------------------------------------------
extern "C" void kernel_launch(void* const* d_in, const int* in_sizes, int n_in,
                              void* d_out, int out_size)
{
    const float* x          = (const float*)d_in[0];
    const int*   ei         = (const int*)d_in[1];
    const float* W0         = (const float*)d_in[2];
    const float* b0         = (const float*)d_in[3];
    const float* W1         = (const float*)d_in[4];
    const float* b1         = (const float*)d_in[5];
    const float* Wout       = (const float*)d_in[6];
    const float* bout       = (const float*)d_in[7];
    const float* hop_att0   = (const float*)d_in[8];
    const float* hop_atts   = (const float*)d_in[9];
    const float* atts       = (const float*)d_in[10];
    const float* hop_biases = (const float*)d_in[11];
    float* out = (float*)d_out;

    float decay[5];
    for (int k = 0; k <= 4; k++) decay[k] = (float)log(1.0 / (k + 1) + 1.0 + 1e-6);

    const int GEMM_GRID = (NN + 63) / 64;
    const int NODE_GRID = (NN + 7) / 8;          // warp per node, 8 warps/block
    const int EDGE_GRID = 13313;                 // ~8 edges per warp (persistent)

    zero0_kernel<<<2048, 256>>>();                                   // idx 0
    gemm1_kernel<<<GEMM_GRID, 256>>>(x, W0, b0);                     // idx 1
    gemm2_hop0_kernel<<<GEMM_GRID, 256>>>(W1, b1, hop_att0,
                                          hop_biases, decay[0]);     // idx 2

    for (int k = 1; k <= 4; k++) {
        int flip = (k & 1);
        edge_att_kernel<<<EDGE_GRID, 256>>>(ei, atts + (size_t)(k - 1) * HH * CC);
        prop_kernel<<<EDGE_GRID, 256>>>(ei, flip);
        hopupd_kernel<<<NODE_GRID, 256>>>(hop_atts + (size_t)(k - 1) * HH * 2 * CC,
                                          hop_biases + (size_t)k * HH,
                                          decay[k - 1], decay[k], flip,
                                          (k < 4) ? 1 : 0);
    }

    out_kernel<<<(NN + 7) / 8, 320>>>(Wout, bout, out);
}

// round 5
// speedup vs baseline: 1.6486x; 1.0307x over previous
#include <cuda_runtime.h>
#include <math.h>

#define NN 50000
#define EE 800000
#define HH 8
#define CC 16
#define HC 128       // H*C

// ---------------- scratch (device globals; no allocation allowed) ----------------
__device__ __align__(16) float g_h1[(size_t)NN * HC];
__device__ __align__(16) float g_hA[(size_t)NN * HC];
__device__ __align__(16) float g_hB[(size_t)NN * HC];
__device__ __align__(16) float g_z [(size_t)NN * HC];
__device__ __align__(16) float g_zs[(size_t)NN * HC];
__device__ __align__(16) float g_ae[(size_t)EE * HH];
__device__ __align__(16) float g_aself[(size_t)NN * HH];
__device__ __align__(16) float g_deg[(size_t)NN * HH];

// fast ELU (FMUL + MUFU.EX2 + FADD + FSEL)
__device__ __forceinline__ float eluf(float x) {
    return x > 0.f ? x : __expf(x) - 1.f;
}
// fast softplus
__device__ __forceinline__ float softplusf(float x) {
    return fmaxf(x, 0.f) + __logf(1.f + __expf(-fabsf(x)));
}

// ---------------- GEMM1: g_h1 = elu(x @ W0 + b0)  (K=256) -------------------------
__global__ void gemm1_kernel(const float* __restrict__ A, const float* __restrict__ W,
                             const float* __restrict__ bias)
{
    __shared__ float As[16][65];
    __shared__ float Bs[16][128];
    const int tid = threadIdx.x;
    const int block_row = blockIdx.x * 64;
    const int row_t = tid >> 5;
    const int col_t = tid & 31;

    float acc[8][4];
    #pragma unroll
    for (int j = 0; j < 8; j++) { acc[j][0]=acc[j][1]=acc[j][2]=acc[j][3]=0.f; }

    for (int k0 = 0; k0 < 256; k0 += 16) {
        {
            int r  = tid >> 2;
            int kk = (tid & 3) << 2;
            int grow = block_row + r;
            float4 v = make_float4(0.f,0.f,0.f,0.f);
            if (grow < NN) v = *(const float4*)&A[(size_t)grow * 256 + k0 + kk];
            As[kk+0][r] = v.x; As[kk+1][r] = v.y; As[kk+2][r] = v.z; As[kk+3][r] = v.w;
        }
        #pragma unroll
        for (int i = 0; i < 2; i++) {
            int idx = tid + (i << 8);
            int bk  = idx >> 5;
            int cc  = (idx & 31) << 2;
            *(float4*)&Bs[bk][cc] = *(const float4*)&W[(size_t)(k0 + bk) * HC + cc];
        }
        __syncthreads();
        #pragma unroll
        for (int k = 0; k < 16; k++) {
            float4 b4 = *(float4*)&Bs[k][col_t << 2];
            #pragma unroll
            for (int j = 0; j < 8; j++) {
                float a = As[k][(row_t << 3) + j];
                acc[j][0] = fmaf(a, b4.x, acc[j][0]);
                acc[j][1] = fmaf(a, b4.y, acc[j][1]);
                acc[j][2] = fmaf(a, b4.z, acc[j][2]);
                acc[j][3] = fmaf(a, b4.w, acc[j][3]);
            }
        }
        __syncthreads();
    }
    float4 bb = *(const float4*)&bias[col_t << 2];
    #pragma unroll
    for (int j = 0; j < 8; j++) {
        int grow = block_row + (row_t << 3) + j;
        if (grow < NN) {
            float4 o;
            o.x = eluf(acc[j][0] + bb.x); o.y = eluf(acc[j][1] + bb.y);
            o.z = eluf(acc[j][2] + bb.z); o.w = eluf(acc[j][3] + bb.w);
            *(float4*)&g_h1[(size_t)grow * HC + (col_t << 2)] = o;
        }
    }
}

// ---------------- GEMM2 + hop-0 epilogue + hop-1 self-attention --------------------
// h -> g_hA ; z -> g_z ; zs -> g_zs ; a_self(hop1) -> g_aself ; deg = a_self
__global__ void gemm2_hop0_kernel(const float* __restrict__ W,
                                  const float* __restrict__ bias,
                                  const float* __restrict__ hop_att0,
                                  const float* __restrict__ hop_bias0,
                                  const float* __restrict__ atts1,
                                  float decay0)
{
    __shared__ float As[16][65];
    __shared__ float Bs[16][128];
    const int tid = threadIdx.x;
    const int block_row = blockIdx.x * 64;
    const int row_t = tid >> 5;
    const int col_t = tid & 31;

    float acc[8][4];
    #pragma unroll
    for (int j = 0; j < 8; j++) { acc[j][0]=acc[j][1]=acc[j][2]=acc[j][3]=0.f; }

    for (int k0 = 0; k0 < 128; k0 += 16) {
        {
            int r  = tid >> 2;
            int kk = (tid & 3) << 2;
            int grow = block_row + r;
            float4 v = make_float4(0.f,0.f,0.f,0.f);
            if (grow < NN) v = *(const float4*)&g_h1[(size_t)grow * HC + k0 + kk];
            As[kk+0][r] = v.x; As[kk+1][r] = v.y; As[kk+2][r] = v.z; As[kk+3][r] = v.w;
        }
        #pragma unroll
        for (int i = 0; i < 2; i++) {
            int idx = tid + (i << 8);
            int bk  = idx >> 5;
            int cc  = (idx & 31) << 2;
            *(float4*)&Bs[bk][cc] = *(const float4*)&W[(size_t)(k0 + bk) * HC + cc];
        }
        __syncthreads();
        #pragma unroll
        for (int k = 0; k < 16; k++) {
            float4 b4 = *(float4*)&Bs[k][col_t << 2];
            #pragma unroll
            for (int j = 0; j < 8; j++) {
                float a = As[k][(row_t << 3) + j];
                acc[j][0] = fmaf(a, b4.x, acc[j][0]);
                acc[j][1] = fmaf(a, b4.y, acc[j][1]);
                acc[j][2] = fmaf(a, b4.z, acc[j][2]);
                acc[j][3] = fmaf(a, b4.w, acc[j][3]);
            }
        }
        __syncthreads();
    }
    float4 bb = *(const float4*)&bias[col_t << 2];
    const int head = col_t >> 2, sub = col_t & 3;
    const float* av = hop_att0 + head * CC + (sub << 2);
    const float av0 = av[0], av1 = av[1], av2 = av[2], av3 = av[3];
    const float* sv = atts1 + head * CC + (sub << 2);
    const float sv0 = sv[0], sv1 = sv[1], sv2 = sv[2], sv3 = sv[3];
    const float hb = hop_bias0[head];
    #pragma unroll
    for (int j = 0; j < 8; j++) {
        int grow = block_row + (row_t << 3) + j;     // uniform per warp
        if (grow < NN) {
            float4 h4;
            h4.x = acc[j][0] + bb.x; h4.y = acc[j][1] + bb.y;
            h4.z = acc[j][2] + bb.z; h4.w = acc[j][3] + bb.w;
            float p = eluf(h4.x)*av0 + eluf(h4.y)*av1 + eluf(h4.z)*av2 + eluf(h4.w)*av3;
            p += __shfl_xor_sync(0xffffffffu, p, 1);
            p += __shfl_xor_sync(0xffffffffu, p, 2);
            float g = p + hb;
            size_t off = (size_t)grow * HC + (col_t << 2);
            *(float4*)&g_hA[off] = h4;
            float4 z4 = make_float4(h4.x*g, h4.y*g, h4.z*g, h4.w*g);
            *(float4*)&g_z[off] = z4;
            float4 zs4 = make_float4(z4.x*decay0, z4.y*decay0, z4.z*decay0, z4.w*decay0);
            *(float4*)&g_zs[off] = zs4;
            // hop-1 self-loop attention: softplus(<atts1, elu(2*zs)>)+1e-6
            float p2 = eluf(2.f*zs4.x)*sv0 + eluf(2.f*zs4.y)*sv1
                     + eluf(2.f*zs4.z)*sv2 + eluf(2.f*zs4.w)*sv3;
            p2 += __shfl_xor_sync(0xffffffffu, p2, 1);
            p2 += __shfl_xor_sync(0xffffffffu, p2, 2);
            if (sub == 0) {
                float a = softplusf(p2) + 1e-6f;
                g_aself[(size_t)grow * HH + head] = a;
                g_deg  [(size_t)grow * HH + head] = a;
            }
        }
    }
}

// ---------------- edge attention over real edges only ------------------------------
__global__ void edge_att_kernel(const int* __restrict__ ei,
                                const float* __restrict__ atts_k)
{
    const int lane = threadIdx.x & 31;
    const int warp0 = (blockIdx.x * blockDim.x + threadIdx.x) >> 5;
    const int nwarps = (gridDim.x * blockDim.x) >> 5;
    const int head = lane >> 2, sub = lane & 3;
    const float* av = atts_k + head * CC + (sub << 2);
    const float av0 = av[0], av1 = av[1], av2 = av[2], av3 = av[3];

    for (int e = warp0; e < EE; e += nwarps) {
        int r = __ldg(&ei[e]);
        int c = __ldg(&ei[EE + e]);
        float4 zi = *(const float4*)&g_zs[(size_t)c * HC + (lane << 2)];
        float4 zj = *(const float4*)&g_zs[(size_t)r * HC + (lane << 2)];
        float p = eluf(zi.x + zj.x)*av0 + eluf(zi.y + zj.y)*av1
                + eluf(zi.z + zj.z)*av2 + eluf(zi.w + zj.w)*av3;
        p += __shfl_xor_sync(0xffffffffu, p, 1);
        p += __shfl_xor_sync(0xffffffffu, p, 2);
        if (sub == 0) {
            float a = softplusf(p) + 1e-6f;
            g_ae[(size_t)e * HH + head] = a;
            atomicAdd(&g_deg[(size_t)c * HH + head], a);
        }
    }
}

// ---------------- prescale: hs = rsqrt(deg) ⊙ h (in place); h_new init = a_self*hs -
__global__ void prescale_kernel(int flip)
{
    float* hprev = flip ? g_hA : g_hB;
    float* hnew  = flip ? g_hB : g_hA;
    int w = (blockIdx.x * blockDim.x + threadIdx.x) >> 5;
    int lane = threadIdx.x & 31;
    if (w >= NN) return;
    int head = lane >> 2;
    float dinv = rsqrtf(g_deg[(size_t)w * HH + head]);      // deg >= 1e-6 always
    float asf  = g_aself[(size_t)w * HH + head];
    size_t off = (size_t)w * HC + (lane << 2);
    float4 h4 = *(const float4*)&hprev[off];
    float4 hs4 = make_float4(h4.x*dinv, h4.y*dinv, h4.z*dinv, h4.w*dinv);
    *(float4*)&hprev[off] = hs4;
    *(float4*)&hnew[off] = make_float4(hs4.x*asf, hs4.y*asf, hs4.z*asf, hs4.w*asf);
}

// ---------------- propagate: h_new[c] += ae * hs[r]  (no per-edge normalization) ---
__global__ void prop_kernel(const int* __restrict__ ei, int flip)
{
    const float* hs = flip ? g_hA : g_hB;
    float* hnew     = flip ? g_hB : g_hA;
    const int lane = threadIdx.x & 31;
    const int warp0 = (blockIdx.x * blockDim.x + threadIdx.x) >> 5;
    const int nwarps = (gridDim.x * blockDim.x) >> 5;
    const int head = lane >> 2;

    for (int e = warp0; e < EE; e += nwarps) {
        int r = __ldg(&ei[e]);
        int c = __ldg(&ei[EE + e]);
        float a = g_ae[(size_t)e * HH + head];
        float4 h4 = *(const float4*)&hs[(size_t)r * HC + (lane << 2)];
        float* dst = &hnew[(size_t)c * HC + (lane << 2)];
        asm volatile("red.global.add.v4.f32 [%0], {%1,%2,%3,%4};"
                     :: "l"(dst), "f"(a * h4.x), "f"(a * h4.y), "f"(a * h4.z), "f"(a * h4.w)
                     : "memory");
    }
}

// ---------------- hop update -------------------------------------------------------
// h = rsqrt(deg) ⊙ h_new (stored in place); g = <hop_atts_k, elu(concat(h, z*dprev))>
// z += h*g ; zs = z*decayk ; then (if next) self-att for next hop -> aself, deg
__global__ void hopupd_kernel(const float* __restrict__ hop_atts_k,
                              const float* __restrict__ hop_bias_k,
                              const float* __restrict__ atts_next,
                              float decay_prev, float decayk, int flip, int do_next)
{
    float* hnew = flip ? g_hB : g_hA;
    int w = (blockIdx.x * blockDim.x + threadIdx.x) >> 5;
    int lane = threadIdx.x & 31;
    if (w >= NN) return;
    int head = lane >> 2, sub = lane & 3;
    size_t off = (size_t)w * HC + (lane << 2);
    float dinv = rsqrtf(g_deg[(size_t)w * HH + head]);
    float4 h4 = *(const float4*)&hnew[off];
    h4.x *= dinv; h4.y *= dinv; h4.z *= dinv; h4.w *= dinv;
    *(float4*)&hnew[off] = h4;                     // final h for next hop's gather
    float4 z4 = *(const float4*)&g_z[off];
    float4 zp = make_float4(z4.x*decay_prev, z4.y*decay_prev,
                            z4.z*decay_prev, z4.w*decay_prev);
    const float* aw  = hop_atts_k + head * (2 * CC) + (sub << 2);
    const float* aw2 = aw + CC;
    float p = eluf(h4.x)*aw[0]  + eluf(h4.y)*aw[1]  + eluf(h4.z)*aw[2]  + eluf(h4.w)*aw[3]
            + eluf(zp.x)*aw2[0] + eluf(zp.y)*aw2[1] + eluf(zp.z)*aw2[2] + eluf(zp.w)*aw2[3];
    p += __shfl_xor_sync(0xffffffffu, p, 1);
    p += __shfl_xor_sync(0xffffffffu, p, 2);
    float g = p + hop_bias_k[head];
    z4.x = fmaf(h4.x, g, z4.x);
    z4.y = fmaf(h4.y, g, z4.y);
    z4.z = fmaf(h4.z, g, z4.z);
    z4.w = fmaf(h4.w, g, z4.w);
    *(float4*)&g_z[off] = z4;
    float4 zs4 = make_float4(z4.x*decayk, z4.y*decayk, z4.z*decayk, z4.w*decayk);
    *(float4*)&g_zs[off] = zs4;
    if (do_next) {
        const float* sv = atts_next + head * CC + (sub << 2);
        float p2 = eluf(2.f*zs4.x)*sv[0] + eluf(2.f*zs4.y)*sv[1]
                 + eluf(2.f*zs4.z)*sv[2] + eluf(2.f*zs4.w)*sv[3];
        p2 += __shfl_xor_sync(0xffffffffu, p2, 1);
        p2 += __shfl_xor_sync(0xffffffffu, p2, 2);
        if (sub == 0) {
            float a = softplusf(p2) + 1e-6f;
            g_aself[(size_t)w * HH + head] = a;
            g_deg  [(size_t)w * HH + head] = a;
        }
    }
}

// ---------------- output: out = elu(z) @ Wout + bout  (N x 40) --------------------
__global__ void out_kernel(const float* __restrict__ Wout,
                           const float* __restrict__ bout,
                           float* __restrict__ out)
{
    __shared__ float Ws[HC * 40];
    __shared__ float bs[40];
    __shared__ float zsm[8][HC];
    int tid = threadIdx.x;
    for (int i = tid; i < HC * 40; i += 320) Ws[i] = Wout[i];
    if (tid < 40) bs[tid] = bout[tid];
    int nbase = blockIdx.x * 8;
    for (int i = tid; i < 8 * HC; i += 320) {
        int ln = i >> 7, c = i & 127;
        int gn = nbase + ln;
        float v = (gn < NN) ? g_z[(size_t)gn * HC + c] : 0.f;
        zsm[ln][c] = eluf(v);
    }
    __syncthreads();
    int ln = tid / 40, o = tid % 40;
    if (ln < 8) {
        int gn = nbase + ln;
        if (gn < NN) {
            float acc = bs[o];
            #pragma unroll 8
            for (int c = 0; c < HC; c++) acc = fmaf(zsm[ln][c], Ws[c * 40 + o], acc);
            out[(size_t)gn * 40 + o] = acc;
        }
    }
}

// ---------------- host orchestration ----------------------------------------------
extern "C" void kernel_launch(void* const* d_in, const int* in_sizes, int n_in,
                              void* d_out, int out_size)
{
    const float* x          = (const float*)d_in[0];
    const int*   ei         = (const int*)d_in[1];
    const float* W0         = (const float*)d_in[2];
    const float* b0         = (const float*)d_in[3];
    const float* W1         = (const float*)d_in[4];
    const float* b1         = (const float*)d_in[5];
    const float* Wout       = (const float*)d_in[6];
    const float* bout       = (const float*)d_in[7];
    const float* hop_att0   = (const float*)d_in[8];
    const float* hop_atts   = (const float*)d_in[9];
    const float* atts       = (const float*)d_in[10];
    const float* hop_biases = (const float*)d_in[11];
    float* out = (float*)d_out;

    float decay[5];
    for (int k = 0; k <= 4; k++) decay[k] = (float)log(1.0 / (k + 1) + 1.0 + 1e-6);

    const int GEMM_GRID = (NN + 63) / 64;
    const int NODE_GRID = (NN + 7) / 8;          // warp per node, 8 warps/block
    const int EDGE_GRID = 12500;                 // 100k warps, 8 edges/warp

    gemm1_kernel<<<GEMM_GRID, 256>>>(x, W0, b0);
    gemm2_hop0_kernel<<<GEMM_GRID, 256>>>(W1, b1, hop_att0, hop_biases,
                                          atts /* hop-1 atts */, decay[0]);

    for (int k = 1; k <= 4; k++) {
        int flip = (k & 1);
        edge_att_kernel<<<EDGE_GRID, 256>>>(ei, atts + (size_t)(k - 1) * HH * CC);
        prescale_kernel<<<NODE_GRID, 256>>>(flip);
        prop_kernel<<<EDGE_GRID, 256>>>(ei, flip);
        hopupd_kernel<<<NODE_GRID, 256>>>(hop_atts + (size_t)(k - 1) * HH * 2 * CC,
                                          hop_biases + (size_t)k * HH,
                                          atts + (size_t)k * HH * CC,
                                          decay[k - 1], decay[k], flip,
                                          (k < 4) ? 1 : 0);
    }

    out_kernel<<<(NN + 7) / 8, 320>>>(Wout, bout, out);
}